// round 1
// baseline (speedup 1.0000x reference)
#include <cuda_runtime.h>
#include <cuda_bf16.h>
#include <math.h>

// Problem constants
#define BATCH 2
#define SEQ   2048
#define HID   1024
#define NHEAD 16
#define HDIM  64
#define TOK   (BATCH*SEQ)          // 4096 rows
#define EPS_LN 1e-12f

// ---------------- scratch (device globals; no runtime allocation) ------------
__device__ float g_xln[TOK * HID];               // LayerNorm output   16 MB
__device__ float g_q[BATCH * NHEAD * SEQ * HDIM]; // Q [B,NH,S,HD]      16 MB
__device__ float g_k[BATCH * NHEAD * SEQ * HDIM]; // K                  16 MB
__device__ float g_v[BATCH * NHEAD * SEQ * HDIM]; // V                  16 MB
__device__ float g_ctx[TOK * HID];               // attention context  16 MB

// =============================== LayerNorm ===================================
// one CTA per row of 1024; 256 threads, each handles one float4
__global__ __launch_bounds__(256)
void ln_kernel(const float* __restrict__ x,
               const float* __restrict__ gamma,
               const float* __restrict__ beta)
{
    const int row = blockIdx.x;
    const int t   = threadIdx.x;
    const float4* xr = reinterpret_cast<const float4*>(x + (size_t)row * HID);
    float4 v = xr[t];

    float s1 = v.x + v.y + v.z + v.w;
    float s2 = v.x*v.x + v.y*v.y + v.z*v.z + v.w*v.w;

    // warp reduce
    #pragma unroll
    for (int o = 16; o; o >>= 1) {
        s1 += __shfl_xor_sync(0xffffffffu, s1, o);
        s2 += __shfl_xor_sync(0xffffffffu, s2, o);
    }
    __shared__ float red1[8], red2[8];
    const int wid = t >> 5, lane = t & 31;
    if (lane == 0) { red1[wid] = s1; red2[wid] = s2; }
    __syncthreads();
    float tot = 0.f, tot2 = 0.f;
    #pragma unroll
    for (int i = 0; i < 8; i++) { tot += red1[i]; tot2 += red2[i]; }

    const float mu   = tot * (1.0f / HID);
    const float var  = tot2 * (1.0f / HID) - mu * mu;
    const float rstd = rsqrtf(var + EPS_LN);

    const float4 g = reinterpret_cast<const float4*>(gamma)[t];
    const float4 b = reinterpret_cast<const float4*>(beta)[t];
    float4 o;
    o.x = (v.x - mu) * rstd * g.x + b.x;
    o.y = (v.y - mu) * rstd * g.y + b.y;
    o.z = (v.z - mu) * rstd * g.z + b.z;
    o.w = (v.w - mu) * rstd * g.w + b.w;
    reinterpret_cast<float4*>(g_xln + (size_t)row * HID)[t] = o;
}

// =============================== GEMM (NT) ===================================
// C[i,j] = sum_k A[i,k] * B[j,k] + bias[j]  (+ epilogue)
// A: [M=4096, K=1024] row-major, B: [N=1024, K=1024] row-major
// MODE 0: write to Q/K/V layout [B,NH,S,HD]
// MODE 1: write C[i*1024+j] = val + resid[i*1024+j]
template<int MODE>
__global__ __launch_bounds__(256)
void gemm_nt(const float* __restrict__ A, const float* __restrict__ B,
             const float* __restrict__ bias, const float* __restrict__ resid,
             float* __restrict__ C)
{
    constexpr int KDIM = 1024;
    const int bn0 = blockIdx.x * 128;
    const int bm0 = blockIdx.y * 128;
    const int t  = threadIdx.x;
    const int tx = t & 15, ty = t >> 4;

    __shared__ float As[128 * 16];
    __shared__ float Bs[128 * 17];   // padded: conflict-free column reads

    float acc[8][8];
    #pragma unroll
    for (int i = 0; i < 8; i++)
        #pragma unroll
        for (int j = 0; j < 8; j++) acc[i][j] = 0.f;

    for (int kt = 0; kt < KDIM / 16; ++kt) {
        // load A tile: 512 float4, 2 per thread
        #pragma unroll
        for (int u = 0; u < 2; ++u) {
            int f = t + 256 * u;
            int row = f >> 2, kg = f & 3;
            float4 av = reinterpret_cast<const float4*>(A + (size_t)(bm0 + row) * KDIM + kt * 16)[kg];
            reinterpret_cast<float4*>(As)[row * 4 + kg] = av;
            float4 bv = reinterpret_cast<const float4*>(B + (size_t)(bn0 + row) * KDIM + kt * 16)[kg];
            Bs[row * 17 + kg * 4 + 0] = bv.x;
            Bs[row * 17 + kg * 4 + 1] = bv.y;
            Bs[row * 17 + kg * 4 + 2] = bv.z;
            Bs[row * 17 + kg * 4 + 3] = bv.w;
        }
        __syncthreads();

        #pragma unroll
        for (int k = 0; k < 16; ++k) {
            float a[8], bb[8];
            #pragma unroll
            for (int ii = 0; ii < 8; ++ii) a[ii]  = As[(ty + 16 * ii) * 16 + k];
            #pragma unroll
            for (int jj = 0; jj < 8; ++jj) bb[jj] = Bs[(tx + 16 * jj) * 17 + k];
            #pragma unroll
            for (int ii = 0; ii < 8; ++ii)
                #pragma unroll
                for (int jj = 0; jj < 8; ++jj)
                    acc[ii][jj] = fmaf(a[ii], bb[jj], acc[ii][jj]);
        }
        __syncthreads();
    }

    // epilogue
    #pragma unroll
    for (int ii = 0; ii < 8; ++ii) {
        const int i = bm0 + ty + 16 * ii;
        #pragma unroll
        for (int jj = 0; jj < 8; ++jj) {
            const int j = bn0 + tx + 16 * jj;
            float val = acc[ii][jj] + bias[j];
            if (MODE == 0) {
                // [B,NH,S,HD]: ((b*16+h)*2048 + s)*64 + d
                const int b = i >> 11, s = i & 2047, h = j >> 6, d = j & 63;
                C[(((size_t)(b * NHEAD + h)) * SEQ + s) * HDIM + d] = val;
            } else {
                C[(size_t)i * HID + j] = val + resid[(size_t)i * HID + j];
            }
        }
    }
}

// =========================== Flash attention =================================
// grid: (32 q-tiles, 32 batch*head); block 256 threads
// 64x64 tiles, online softmax. K tile rotate-swizzled; reused as P buffer.
__global__ __launch_bounds__(256)
void attn_kernel(const float* __restrict__ mask)
{
    const int qt = blockIdx.x;        // 0..31
    const int bh = blockIdx.y;        // 0..31
    const int b  = bh >> 4;
    const int h  = bh & 15;

    const float* Qg = g_q + (size_t)bh * SEQ * HDIM + (size_t)qt * 64 * HDIM;
    const float* Kg = g_k + (size_t)bh * SEQ * HDIM;
    const float* Vg = g_v + (size_t)bh * SEQ * HDIM;
    const float* mk = mask + (size_t)b * SEQ;

    __shared__ float Qs[64 * 64];
    __shared__ float Ks[64 * 64];   // rotate-swizzled K; reused for P
    __shared__ float Vs[64 * 64];

    const int t  = threadIdx.x;
    const int tx = t & 15, ty = t >> 4;

    // load Q tile (layout identical -> straight float4 copy)
    #pragma unroll
    for (int u = 0; u < 4; ++u) {
        int f = t + 256 * u;
        reinterpret_cast<float4*>(Qs)[f] = reinterpret_cast<const float4*>(Qg)[f];
    }

    float o[4][4], m[4], l[4];
    #pragma unroll
    for (int ii = 0; ii < 4; ++ii) {
        m[ii] = -1e30f; l[ii] = 0.f;
        #pragma unroll
        for (int jj = 0; jj < 4; ++jj) o[ii][jj] = 0.f;
    }

    for (int kt = 0; kt < SEQ / 64; ++kt) {
        __syncthreads();   // protect Ks(P)/Vs from previous iteration readers
        #pragma unroll
        for (int u = 0; u < 4; ++u) {
            int f = t + 256 * u;
            int c = f >> 4, dg = (f & 15) * 4;
            float4 kv = reinterpret_cast<const float4*>(Kg + (size_t)kt * 64 * HDIM)[f];
            Ks[c * 64 + ((dg + 0 + c) & 63)] = kv.x;
            Ks[c * 64 + ((dg + 1 + c) & 63)] = kv.y;
            Ks[c * 64 + ((dg + 2 + c) & 63)] = kv.z;
            Ks[c * 64 + ((dg + 3 + c) & 63)] = kv.w;
            reinterpret_cast<float4*>(Vs)[f] =
                reinterpret_cast<const float4*>(Vg + (size_t)kt * 64 * HDIM)[f];
        }
        __syncthreads();

        // S = Q K^T (64-deep)
        float s[4][4];
        #pragma unroll
        for (int ii = 0; ii < 4; ++ii)
            #pragma unroll
            for (int jj = 0; jj < 4; ++jj) s[ii][jj] = 0.f;

        #pragma unroll 8
        for (int d = 0; d < 64; ++d) {
            float a[4], bf[4];
            #pragma unroll
            for (int ii = 0; ii < 4; ++ii) a[ii] = Qs[(ty + 16 * ii) * 64 + d];
            #pragma unroll
            for (int jj = 0; jj < 4; ++jj) {
                const int c = tx + 16 * jj;
                bf[jj] = Ks[c * 64 + ((d + c) & 63)];
            }
            #pragma unroll
            for (int ii = 0; ii < 4; ++ii)
                #pragma unroll
                for (int jj = 0; jj < 4; ++jj)
                    s[ii][jj] = fmaf(a[ii], bf[jj], s[ii][jj]);
        }

        // scale + mask + online softmax (per-row stats across 16 lanes)
        #pragma unroll
        for (int ii = 0; ii < 4; ++ii) {
            float rm = -1e30f;
            #pragma unroll
            for (int jj = 0; jj < 4; ++jj) {
                const int key = kt * 64 + tx + 16 * jj;
                s[ii][jj] = s[ii][jj] * 0.125f + __ldg(&mk[key]);
                rm = fmaxf(rm, s[ii][jj]);
            }
            #pragma unroll
            for (int off = 8; off; off >>= 1)
                rm = fmaxf(rm, __shfl_xor_sync(0xffffffffu, rm, off, 16));
            const float mn = fmaxf(m[ii], rm);
            const float alpha = __expf(m[ii] - mn);
            m[ii] = mn;
            float rs = 0.f;
            #pragma unroll
            for (int jj = 0; jj < 4; ++jj) {
                const float p = __expf(s[ii][jj] - mn);
                s[ii][jj] = p; rs += p;
            }
            #pragma unroll
            for (int off = 8; off; off >>= 1)
                rs += __shfl_xor_sync(0xffffffffu, rs, off, 16);
            l[ii] = l[ii] * alpha + rs;
            #pragma unroll
            for (int jj = 0; jj < 4; ++jj) o[ii][jj] *= alpha;
        }

        __syncthreads();  // everyone done reading Ks -> safe to overwrite with P
        #pragma unroll
        for (int ii = 0; ii < 4; ++ii)
            #pragma unroll
            for (int jj = 0; jj < 4; ++jj) {
                const int r = ty + 16 * ii, c = tx + 16 * jj;
                Ks[r * 64 + ((c + r) & 63)] = s[ii][jj];
            }
        __syncthreads();

        // O += P V
        #pragma unroll 8
        for (int kk = 0; kk < 64; ++kk) {
            float p[4], vv[4];
            #pragma unroll
            for (int ii = 0; ii < 4; ++ii) {
                const int r = ty + 16 * ii;
                p[ii] = Ks[r * 64 + ((kk + r) & 63)];
            }
            #pragma unroll
            for (int jj = 0; jj < 4; ++jj) vv[jj] = Vs[kk * 64 + tx + 16 * jj];
            #pragma unroll
            for (int ii = 0; ii < 4; ++ii)
                #pragma unroll
                for (int jj = 0; jj < 4; ++jj)
                    o[ii][jj] = fmaf(p[ii], vv[jj], o[ii][jj]);
        }
    }

    // epilogue: ctx [B,S,H] with column h*64+d
    #pragma unroll
    for (int ii = 0; ii < 4; ++ii) {
        const float inv = 1.0f / l[ii];
        const int srow = qt * 64 + ty + 16 * ii;
        #pragma unroll
        for (int jj = 0; jj < 4; ++jj) {
            const int d = tx + 16 * jj;
            g_ctx[((size_t)(b * SEQ + srow)) * HID + h * HDIM + d] = o[ii][jj] * inv;
        }
    }
}

// ================================ launch =====================================
extern "C" void kernel_launch(void* const* d_in, const int* in_sizes, int n_in,
                              void* d_out, int out_size)
{
    const float* hs    = (const float*)d_in[0];
    const float* mask  = (const float*)d_in[1];
    const float* wq    = (const float*)d_in[2];
    const float* bq    = (const float*)d_in[3];
    const float* wk    = (const float*)d_in[4];
    const float* bk    = (const float*)d_in[5];
    const float* wv    = (const float*)d_in[6];
    const float* bv    = (const float*)d_in[7];
    const float* wo    = (const float*)d_in[8];
    const float* bo    = (const float*)d_in[9];
    const float* gamma = (const float*)d_in[10];
    const float* beta  = (const float*)d_in[11];
    float* out = (float*)d_out;

    // device pointers to scratch globals (query only — no allocation)
    float *p_xln, *p_q, *p_k, *p_v, *p_ctx;
    cudaGetSymbolAddress((void**)&p_xln, g_xln);
    cudaGetSymbolAddress((void**)&p_q,   g_q);
    cudaGetSymbolAddress((void**)&p_k,   g_k);
    cudaGetSymbolAddress((void**)&p_v,   g_v);
    cudaGetSymbolAddress((void**)&p_ctx, g_ctx);

    // 1. LayerNorm
    ln_kernel<<<TOK, 256>>>(hs, gamma, beta);

    // 2. Q/K/V projections
    dim3 gg(HID / 128, TOK / 128);   // (8, 32)
    gemm_nt<0><<<gg, 256>>>(p_xln, wq, bq, nullptr, p_q);
    gemm_nt<0><<<gg, 256>>>(p_xln, wk, bk, nullptr, p_k);
    gemm_nt<0><<<gg, 256>>>(p_xln, wv, bv, nullptr, p_v);

    // 3. attention
    dim3 ga(SEQ / 64, BATCH * NHEAD);  // (32, 32)
    attn_kernel<<<ga, 256>>>(mask);

    // 4. output projection + bias + residual
    gemm_nt<1><<<gg, 256>>>(p_ctx, wo, bo, hs, out);
}

// round 2
// speedup vs baseline: 4.2527x; 4.2527x over previous
#include <cuda_runtime.h>
#include <cuda_bf16.h>
#include <math.h>
#include <stdint.h>

// Problem constants
#define BATCH 2
#define SEQ   2048
#define HID   1024
#define NHEAD 16
#define HDIM  64
#define TOK   (BATCH*SEQ)          // 4096 rows
#define EPS_LN 1e-12f

// ---------------- scratch (device globals; no runtime allocation) ------------
__device__ float g_xln[TOK * HID];                // LayerNorm output
__device__ float g_q[BATCH * NHEAD * SEQ * HDIM]; // Q [B,NH,S,HD]
__device__ float g_k[BATCH * NHEAD * SEQ * HDIM]; // K
__device__ float g_v[BATCH * NHEAD * SEQ * HDIM]; // V
__device__ float g_ctx[TOK * HID];                // attention context

// ---------------- helpers ----------------------------------------------------
__device__ __forceinline__ float f2tf32(float x) {
    uint32_t u;
    asm("cvt.rna.tf32.f32 %0, %1;" : "=r"(u) : "f"(x));
    return __uint_as_float(u);
}

__device__ __forceinline__ void mma_tf32(float* c, const uint32_t* a,
                                         uint32_t b0, uint32_t b1) {
    asm volatile(
        "mma.sync.aligned.m16n8k8.row.col.f32.tf32.tf32.f32 "
        "{%0,%1,%2,%3}, {%4,%5,%6,%7}, {%8,%9}, {%0,%1,%2,%3};"
        : "+f"(c[0]), "+f"(c[1]), "+f"(c[2]), "+f"(c[3])
        : "r"(a[0]), "r"(a[1]), "r"(a[2]), "r"(a[3]), "r"(b0), "r"(b1));
}

// =============================== LayerNorm ===================================
__global__ __launch_bounds__(256)
void ln_kernel(const float* __restrict__ x,
               const float* __restrict__ gamma,
               const float* __restrict__ beta)
{
    const int row = blockIdx.x;
    const int t   = threadIdx.x;
    const float4* xr = reinterpret_cast<const float4*>(x + (size_t)row * HID);
    float4 v = xr[t];

    float s1 = v.x + v.y + v.z + v.w;
    float s2 = v.x*v.x + v.y*v.y + v.z*v.z + v.w*v.w;

    #pragma unroll
    for (int o = 16; o; o >>= 1) {
        s1 += __shfl_xor_sync(0xffffffffu, s1, o);
        s2 += __shfl_xor_sync(0xffffffffu, s2, o);
    }
    __shared__ float red1[8], red2[8];
    const int wid = t >> 5, lane = t & 31;
    if (lane == 0) { red1[wid] = s1; red2[wid] = s2; }
    __syncthreads();
    float tot = 0.f, tot2 = 0.f;
    #pragma unroll
    for (int i = 0; i < 8; i++) { tot += red1[i]; tot2 += red2[i]; }

    const float mu   = tot * (1.0f / HID);
    const float var  = tot2 * (1.0f / HID) - mu * mu;
    const float rstd = rsqrtf(var + EPS_LN);

    const float4 g = reinterpret_cast<const float4*>(gamma)[t];
    const float4 b = reinterpret_cast<const float4*>(beta)[t];
    float4 o;
    o.x = (v.x - mu) * rstd * g.x + b.x;
    o.y = (v.y - mu) * rstd * g.y + b.y;
    o.z = (v.z - mu) * rstd * g.z + b.z;
    o.w = (v.w - mu) * rstd * g.w + b.w;
    reinterpret_cast<float4*>(g_xln + (size_t)row * HID)[t] = o;
}

// ============================ tf32 GEMM (NT) =================================
// C[i,j] = sum_k A[i,k]*B[j,k] + bias[j]  (+epilogue)
// 128x128 CTA tile, K-tile 32. 8 warps (2 M x 4 N), warp tile 64x32,
// m16n8k8 atoms 4x4 per warp. Smem stride 36 floats -> all fragment LDS
// patterns hit banks (4g+tig)%32: conflict-free.
template<int MODE>
__global__ __launch_bounds__(256)
void gemm_tc(const float* __restrict__ A, const float* __restrict__ B,
             const float* __restrict__ bias, const float* __restrict__ resid,
             float* __restrict__ C)
{
    constexpr int KD = 1024;
    __shared__ float As[128 * 36];
    __shared__ float Bs[128 * 36];

    const int t    = threadIdx.x;
    const int w    = t >> 5, lane = t & 31;
    const int g    = lane >> 2, tig = lane & 3;
    const int wm   = (w & 1) * 64, wn = (w >> 1) * 32;
    const int bm0  = blockIdx.y * 128, bn0 = blockIdx.x * 128;

    float acc[4][4][4];
    #pragma unroll
    for (int mi = 0; mi < 4; ++mi)
        #pragma unroll
        for (int ni = 0; ni < 4; ++ni)
            #pragma unroll
            for (int cc = 0; cc < 4; ++cc) acc[mi][ni][cc] = 0.f;

    for (int kt = 0; kt < KD / 32; ++kt) {
        __syncthreads();
        #pragma unroll
        for (int u = 0; u < 4; ++u) {
            int f = t + 256 * u;
            int row = f >> 3, c4 = (f & 7) * 4;
            float4 av = *reinterpret_cast<const float4*>(
                A + (size_t)(bm0 + row) * KD + kt * 32 + c4);
            As[row * 36 + c4 + 0] = f2tf32(av.x);
            As[row * 36 + c4 + 1] = f2tf32(av.y);
            As[row * 36 + c4 + 2] = f2tf32(av.z);
            As[row * 36 + c4 + 3] = f2tf32(av.w);
            float4 bv = *reinterpret_cast<const float4*>(
                B + (size_t)(bn0 + row) * KD + kt * 32 + c4);
            Bs[row * 36 + c4 + 0] = f2tf32(bv.x);
            Bs[row * 36 + c4 + 1] = f2tf32(bv.y);
            Bs[row * 36 + c4 + 2] = f2tf32(bv.z);
            Bs[row * 36 + c4 + 3] = f2tf32(bv.w);
        }
        __syncthreads();

        #pragma unroll
        for (int kk = 0; kk < 4; ++kk) {
            uint32_t a[4][4], b[4][2];
            #pragma unroll
            for (int mi = 0; mi < 4; ++mi) {
                int r0 = wm + mi * 16 + g;
                a[mi][0] = __float_as_uint(As[r0 * 36 + kk * 8 + tig]);
                a[mi][1] = __float_as_uint(As[(r0 + 8) * 36 + kk * 8 + tig]);
                a[mi][2] = __float_as_uint(As[r0 * 36 + kk * 8 + tig + 4]);
                a[mi][3] = __float_as_uint(As[(r0 + 8) * 36 + kk * 8 + tig + 4]);
            }
            #pragma unroll
            for (int ni = 0; ni < 4; ++ni) {
                int rn = wn + ni * 8 + g;
                b[ni][0] = __float_as_uint(Bs[rn * 36 + kk * 8 + tig]);
                b[ni][1] = __float_as_uint(Bs[rn * 36 + kk * 8 + tig + 4]);
            }
            #pragma unroll
            for (int mi = 0; mi < 4; ++mi)
                #pragma unroll
                for (int ni = 0; ni < 4; ++ni)
                    mma_tf32(acc[mi][ni], a[mi], b[ni][0], b[ni][1]);
        }
    }

    // epilogue: c0:(g,2tig) c1:(g,2tig+1) c2:(g+8,2tig) c3:(g+8,2tig+1)
    #pragma unroll
    for (int mi = 0; mi < 4; ++mi) {
        const int i0 = bm0 + wm + mi * 16 + g;
        #pragma unroll
        for (int ni = 0; ni < 4; ++ni) {
            const int j0 = bn0 + wn + ni * 8 + 2 * tig;
            #pragma unroll
            for (int cc = 0; cc < 4; ++cc) {
                const int i = i0 + (cc >= 2 ? 8 : 0);
                const int j = j0 + (cc & 1);
                float val = acc[mi][ni][cc] + bias[j];
                if (MODE == 0) {
                    const int bb = i >> 11, s = i & 2047, h = j >> 6, d = j & 63;
                    C[(((size_t)(bb * NHEAD + h)) * SEQ + s) * HDIM + d] = val;
                } else {
                    C[(size_t)i * HID + j] = val + resid[(size_t)i * HID + j];
                }
            }
        }
    }
}

// ======================= tensor-core flash attention =========================
// CTA: 128 q-rows x one (b,h). 8 warps, each owns 16 complete q-rows -> softmax
// stats warp-local. K-tile 64 keys. All GEMMs m16n8k8 tf32.
#define ATTN_SMEM_FLOATS (128*68 + 64*68 + 64*72 + 128*68 + 64)
#define ATTN_SMEM_BYTES  (ATTN_SMEM_FLOATS * 4)

__global__ __launch_bounds__(256)
void attn_tc(const float* __restrict__ mask)
{
    extern __shared__ float sm[];
    float* Qs  = sm;                 // [128][68]
    float* Ks  = Qs + 128 * 68;      // [64][68]
    float* Vs  = Ks + 64 * 68;       // [64][72]
    float* Ps  = Vs + 64 * 72;       // [128][68]
    float* Msk = Ps + 128 * 68;      // [64]

    const int qt = blockIdx.x, bh = blockIdx.y;
    const int b  = bh >> 4, h = bh & 15;
    const int q0 = qt * 128;
    const float* Qg = g_q + (size_t)bh * SEQ * HDIM + (size_t)q0 * HDIM;
    const float* Kg = g_k + (size_t)bh * SEQ * HDIM;
    const float* Vg = g_v + (size_t)bh * SEQ * HDIM;
    const float* mk = mask + (size_t)b * SEQ;

    const int t = threadIdx.x, w = t >> 5, lane = t & 31;
    const int g = lane >> 2, tig = lane & 3;

    // load Q tile 128x64 -> tf32
    #pragma unroll
    for (int u = 0; u < 8; ++u) {
        int f = t + 256 * u;
        int row = f >> 4, c4 = (f & 15) * 4;
        float4 qv = *reinterpret_cast<const float4*>(Qg + (size_t)row * HDIM + c4);
        Qs[row * 68 + c4 + 0] = f2tf32(qv.x);
        Qs[row * 68 + c4 + 1] = f2tf32(qv.y);
        Qs[row * 68 + c4 + 2] = f2tf32(qv.z);
        Qs[row * 68 + c4 + 3] = f2tf32(qv.w);
    }

    float oacc[8][4];
    #pragma unroll
    for (int di = 0; di < 8; ++di)
        #pragma unroll
        for (int cc = 0; cc < 4; ++cc) oacc[di][cc] = 0.f;
    float mrow[2] = { -1e30f, -1e30f };
    float lrow[2] = { 0.f, 0.f };

    const int r0 = w * 16 + g;

    for (int kt = 0; kt < SEQ / 64; ++kt) {
        __syncthreads();   // prior iteration fully done with Ks/Vs/Ps/Msk
        #pragma unroll
        for (int u = 0; u < 4; ++u) {
            int f = t + 256 * u;
            int row = f >> 4, c4 = (f & 15) * 4;
            float4 kv = *reinterpret_cast<const float4*>(
                Kg + (size_t)(kt * 64 + row) * HDIM + c4);
            Ks[row * 68 + c4 + 0] = f2tf32(kv.x);
            Ks[row * 68 + c4 + 1] = f2tf32(kv.y);
            Ks[row * 68 + c4 + 2] = f2tf32(kv.z);
            Ks[row * 68 + c4 + 3] = f2tf32(kv.w);
            float4 vv = *reinterpret_cast<const float4*>(
                Vg + (size_t)(kt * 64 + row) * HDIM + c4);
            Vs[row * 72 + c4 + 0] = f2tf32(vv.x);
            Vs[row * 72 + c4 + 1] = f2tf32(vv.y);
            Vs[row * 72 + c4 + 2] = f2tf32(vv.z);
            Vs[row * 72 + c4 + 3] = f2tf32(vv.w);
        }
        if (t < 16) {
            float4 mv = *reinterpret_cast<const float4*>(mk + kt * 64 + t * 4);
            Msk[t * 4 + 0] = mv.x; Msk[t * 4 + 1] = mv.y;
            Msk[t * 4 + 2] = mv.z; Msk[t * 4 + 3] = mv.w;
        }
        __syncthreads();

        // ---- S = Q K^T  (16 rows x 64 keys per warp) ----
        float sacc[8][4];
        #pragma unroll
        for (int ni = 0; ni < 8; ++ni)
            #pragma unroll
            for (int cc = 0; cc < 4; ++cc) sacc[ni][cc] = 0.f;

        #pragma unroll
        for (int kk = 0; kk < 8; ++kk) {
            uint32_t a[4];
            a[0] = __float_as_uint(Qs[r0 * 68 + kk * 8 + tig]);
            a[1] = __float_as_uint(Qs[(r0 + 8) * 68 + kk * 8 + tig]);
            a[2] = __float_as_uint(Qs[r0 * 68 + kk * 8 + tig + 4]);
            a[3] = __float_as_uint(Qs[(r0 + 8) * 68 + kk * 8 + tig + 4]);
            #pragma unroll
            for (int ni = 0; ni < 8; ++ni) {
                uint32_t b0 = __float_as_uint(Ks[(ni * 8 + g) * 68 + kk * 8 + tig]);
                uint32_t b1 = __float_as_uint(Ks[(ni * 8 + g) * 68 + kk * 8 + tig + 4]);
                mma_tf32(sacc[ni], a, b0, b1);
            }
        }

        // ---- online softmax (rows g and g+8; cols spread over tig quads) ----
        #pragma unroll
        for (int r = 0; r < 2; ++r) {
            float rm = -1e30f;
            #pragma unroll
            for (int ni = 0; ni < 8; ++ni)
                #pragma unroll
                for (int cc = 0; cc < 2; ++cc) {
                    float v = sacc[ni][r * 2 + cc] * 0.125f
                            + Msk[ni * 8 + 2 * tig + cc];
                    sacc[ni][r * 2 + cc] = v;
                    rm = fmaxf(rm, v);
                }
            rm = fmaxf(rm, __shfl_xor_sync(0xffffffffu, rm, 1));
            rm = fmaxf(rm, __shfl_xor_sync(0xffffffffu, rm, 2));
            const float mn    = fmaxf(mrow[r], rm);
            const float alpha = __expf(mrow[r] - mn);
            mrow[r] = mn;
            float rs = 0.f;
            #pragma unroll
            for (int ni = 0; ni < 8; ++ni)
                #pragma unroll
                for (int cc = 0; cc < 2; ++cc) {
                    float p = __expf(sacc[ni][r * 2 + cc] - mn);
                    sacc[ni][r * 2 + cc] = p;
                    rs += p;
                }
            rs += __shfl_xor_sync(0xffffffffu, rs, 1);
            rs += __shfl_xor_sync(0xffffffffu, rs, 2);
            lrow[r] = lrow[r] * alpha + rs;
            #pragma unroll
            for (int di = 0; di < 8; ++di) {
                oacc[di][r * 2 + 0] *= alpha;
                oacc[di][r * 2 + 1] *= alpha;
            }
        }

        // ---- P -> smem (tf32) ----
        #pragma unroll
        for (int ni = 0; ni < 8; ++ni) {
            int cb = ni * 8 + 2 * tig;
            Ps[r0 * 68 + cb]           = f2tf32(sacc[ni][0]);
            Ps[r0 * 68 + cb + 1]       = f2tf32(sacc[ni][1]);
            Ps[(r0 + 8) * 68 + cb]     = f2tf32(sacc[ni][2]);
            Ps[(r0 + 8) * 68 + cb + 1] = f2tf32(sacc[ni][3]);
        }
        __syncthreads();

        // ---- O += P V ----
        #pragma unroll
        for (int kk = 0; kk < 8; ++kk) {
            uint32_t a[4];
            a[0] = __float_as_uint(Ps[r0 * 68 + kk * 8 + tig]);
            a[1] = __float_as_uint(Ps[(r0 + 8) * 68 + kk * 8 + tig]);
            a[2] = __float_as_uint(Ps[r0 * 68 + kk * 8 + tig + 4]);
            a[3] = __float_as_uint(Ps[(r0 + 8) * 68 + kk * 8 + tig + 4]);
            #pragma unroll
            for (int di = 0; di < 8; ++di) {
                uint32_t b0 = __float_as_uint(Vs[(kk * 8 + tig) * 72 + di * 8 + g]);
                uint32_t b1 = __float_as_uint(Vs[(kk * 8 + tig + 4) * 72 + di * 8 + g]);
                mma_tf32(oacc[di], a, b0, b1);
            }
        }
    }

    // ---- epilogue ----
    const float inv0 = 1.0f / lrow[0];
    const float inv1 = 1.0f / lrow[1];
    const int row0 = q0 + r0;
    const size_t base0 = ((size_t)(b * SEQ + row0)) * HID;
    const size_t base1 = ((size_t)(b * SEQ + row0 + 8)) * HID;
    #pragma unroll
    for (int di = 0; di < 8; ++di) {
        const int c = h * 64 + di * 8 + 2 * tig;
        g_ctx[base0 + c]     = oacc[di][0] * inv0;
        g_ctx[base0 + c + 1] = oacc[di][1] * inv0;
        g_ctx[base1 + c]     = oacc[di][2] * inv1;
        g_ctx[base1 + c + 1] = oacc[di][3] * inv1;
    }
}

// ================================ launch =====================================
extern "C" void kernel_launch(void* const* d_in, const int* in_sizes, int n_in,
                              void* d_out, int out_size)
{
    const float* hs    = (const float*)d_in[0];
    const float* mask  = (const float*)d_in[1];
    const float* wq    = (const float*)d_in[2];
    const float* bq    = (const float*)d_in[3];
    const float* wk    = (const float*)d_in[4];
    const float* bk    = (const float*)d_in[5];
    const float* wv    = (const float*)d_in[6];
    const float* bv    = (const float*)d_in[7];
    const float* wo    = (const float*)d_in[8];
    const float* bo    = (const float*)d_in[9];
    const float* gamma = (const float*)d_in[10];
    const float* beta  = (const float*)d_in[11];
    float* out = (float*)d_out;

    float *p_xln, *p_q, *p_k, *p_v, *p_ctx;
    cudaGetSymbolAddress((void**)&p_xln, g_xln);
    cudaGetSymbolAddress((void**)&p_q,   g_q);
    cudaGetSymbolAddress((void**)&p_k,   g_k);
    cudaGetSymbolAddress((void**)&p_v,   g_v);
    cudaGetSymbolAddress((void**)&p_ctx, g_ctx);

    cudaFuncSetAttribute(attn_tc, cudaFuncAttributeMaxDynamicSharedMemorySize,
                         ATTN_SMEM_BYTES);

    // 1. LayerNorm
    ln_kernel<<<TOK, 256>>>(hs, gamma, beta);

    // 2. Q/K/V projections (tf32 tensor cores)
    dim3 gg(HID / 128, TOK / 128);   // (8, 32)
    gemm_tc<0><<<gg, 256>>>(p_xln, wq, bq, nullptr, p_q);
    gemm_tc<0><<<gg, 256>>>(p_xln, wk, bk, nullptr, p_k);
    gemm_tc<0><<<gg, 256>>>(p_xln, wv, bv, nullptr, p_v);

    // 3. attention (tensor-core flash)
    dim3 ga(SEQ / 128, BATCH * NHEAD);  // (16, 32)
    attn_tc<<<ga, 256, ATTN_SMEM_BYTES>>>(mask);

    // 4. output projection + bias + residual
    gemm_tc<1><<<gg, 256>>>(p_ctx, wo, bo, hs, out);
}